// round 14
// baseline (speedup 1.0000x reference)
#include <cuda_runtime.h>
#include <cuda_bf16.h>
#include <cstdint>

#define NN 50000
#define NE 600000
#define DIM 128
#define KC0 256
#define BN_EPS 1e-5f

typedef __nv_bfloat16 bf16;

// ============================ scratch globals ================================
__device__ int g_deg[NN];
__device__ int g_off[NN + 1];
__device__ int g_cursor[NN];
__device__ int g_eid[NE];
__device__ int g_aggval[64];
__device__ int g_aggflag[64];
__device__ int g_bar0, g_bar1, g_done, g_done2;
__device__ bf16 g_combh[NN * KC0];
__device__ bf16 g_combl[NN * KC0];
__device__ bf16 g_h0h[NN * DIM];
__device__ bf16 g_h0l[NN * DIM];
__device__ bf16 g_h1h[NN * DIM];
__device__ bf16 g_h1l[NN * DIM];
__device__ bf16 g_w0h[DIM * KC0];
__device__ bf16 g_w0l[DIM * KC0];
__device__ bf16 g_wf1h[DIM * DIM];
__device__ bf16 g_wf1l[DIM * DIM];
__device__ bf16 g_wf2h[DIM * DIM];
__device__ bf16 g_wf2l[DIM * DIM];
__device__ float g_ubias[DIM * DIM];
__device__ float g_bf1[DIM];
__device__ float g_bf2[DIM];
__device__ float g_stats[3 * 2 * DIM];
__device__ int g_is64;

__device__ __forceinline__ uint32_t pack2bf(float a, float b) {
    __nv_bfloat162 t = __floats2bfloat162_rn(a, b);
    return *reinterpret_cast<uint32_t*>(&t);
}

__device__ __forceinline__ uint32_t smem_u32(const void* p) {
    uint32_t a;
    asm("{ .reg .u64 t; cvta.to.shared.u64 t, %1; cvt.u32.u64 %0, t; }"
        : "=r"(a) : "l"(p));
    return a;
}

#define CP_ASYNC16(dst, src, sz) \
    asm volatile("cp.async.ca.shared.global [%0], [%1], 16, %2;" \
                 :: "r"(dst), "l"(src), "r"(sz))
#define CP_COMMIT() asm volatile("cp.async.commit_group;" ::: "memory")
#define CP_WAIT0() asm volatile("cp.async.wait_group 0;" ::: "memory")
#define CP_WAIT1() asm volatile("cp.async.wait_group 1;" ::: "memory")

__device__ __forceinline__ int load_idx(const void* p, int i) {
    if (g_is64) return (int)((const long long*)p)[i];
    return ((const int*)p)[i];
}

// grid-wide spin barrier for persistent kernel (all blocks resident)
__device__ __forceinline__ void grid_bar(int* ctr, int nblk) {
    __threadfence();
    __syncthreads();
    if (threadIdx.x == 0) {
        atomicAdd(ctr, 1);
        while (atomicAdd(ctr, 0) < nblk) {}
    }
    __syncthreads();
}

// == prep: detect dtype + zero small scratch + split W0 + per-graph ubias ====
__global__ void prep_kernel(const int* __restrict__ ei32,
                            const float* __restrict__ W0,
                            const float* __restrict__ b0,
                            const float* __restrict__ u, int nG) {
    int gtid = blockIdx.x * blockDim.x + threadIdx.x;
    int stride = gridDim.x * blockDim.x;
    if (blockIdx.x == 0) {
        __shared__ int any;
        if (threadIdx.x == 0) any = 0;
        __syncthreads();
        for (int i = threadIdx.x; i < 1024; i += blockDim.x)
            if (ei32[2 * i + 1] != 0) atomicOr(&any, 1);
        __syncthreads();
        if (threadIdx.x == 0) g_is64 = (any == 0) ? 1 : 0;
    }
    for (int j = gtid; j < 3 * 2 * DIM; j += stride) g_stats[j] = 0.f;
    for (int j = gtid; j < 64; j += stride) g_aggflag[j] = 0;
    if (gtid == 0) { g_bar0 = 0; g_bar1 = 0; g_done = 0; g_done2 = 0; }
    for (int i = gtid; i < DIM * KC0; i += stride) {
        int row = i >> 8;
        int col = i & 255;
        float w = W0[row * 384 + col];
        bf16 h = __float2bfloat16_rn(w);
        g_w0h[i] = h;
        g_w0l[i] = __float2bfloat16_rn(w - __bfloat162float(h));
    }
    int g = (int)blockIdx.x - 128;
    if (g >= 0 && g < nG && threadIdx.x < 128) {
        __shared__ float su[128];
        int j = threadIdx.x;
        su[j] = u[g * 128 + j];
        __syncthreads();
        const float* w = W0 + (size_t)j * 384 + 256;
        float acc = b0[j];
#pragma unroll 4
        for (int k = 0; k < 128; k++) acc += su[k] * w[k];
        g_ubias[g * 128 + j] = acc;
    }
}

__device__ __forceinline__ void split4(float4 v, uint2& H, uint2& L) {
    bf16 h0 = __float2bfloat16_rn(v.x);
    bf16 h1 = __float2bfloat16_rn(v.y);
    bf16 h2 = __float2bfloat16_rn(v.z);
    bf16 h3 = __float2bfloat16_rn(v.w);
    float l0 = v.x - __bfloat162float(h0);
    float l1 = v.y - __bfloat162float(h1);
    float l2 = v.z - __bfloat162float(h2);
    float l3 = v.w - __bfloat162float(h3);
    __nv_bfloat162 p01; p01.x = h0; p01.y = h1;
    __nv_bfloat162 p23; p23.x = h2; p23.y = h3;
    H.x = *reinterpret_cast<uint32_t*>(&p01);
    H.y = *reinterpret_cast<uint32_t*>(&p23);
    L.x = pack2bf(l0, l1);
    L.y = pack2bf(l2, l3);
}

// == persistent: zero-deg + hist + scan + CSR fill + gather/comb =============
__global__ void __launch_bounds__(1024, 1)
graph_kernel(const void* __restrict__ ei,
             const float* __restrict__ ea,
             const float* __restrict__ x,
             int nE, int n, int nb) {
    int tid = threadIdx.x;
    int bid = blockIdx.x;
    int lane = tid & 31;
    int wid = tid >> 5;
    int nblk = (int)gridDim.x;
    int stride = nblk * 1024;

    // phase 0: zero degree counters
    for (int j = bid * 1024 + tid; j < n; j += stride) g_deg[j] = 0;
    grid_bar(&g_bar0, nblk);

    // phase 1: histogram
    for (int e = bid * 1024 + tid; e < nE; e += stride) {
        int src = load_idx(ei, e);
        if ((unsigned)src < (unsigned)n) atomicAdd(&g_deg[src], 1);
    }
    grid_bar(&g_bar1, nblk);

    // phase 2: scan with decoupled lookback (blocks < nb)
    if (bid < nb) {
        __shared__ int wsum[32];
        __shared__ int bprefix;
        int idx = bid * 1024 + tid;
        int v = (idx < n) ? g_deg[idx] : 0;
        int xs = v;
#pragma unroll
        for (int off = 1; off < 32; off <<= 1) {
            int t = __shfl_up_sync(0xffffffffu, xs, off);
            if (lane >= off) xs += t;
        }
        if (lane == 31) wsum[wid] = xs;
        __syncthreads();
        if (wid == 0) {
            int w = wsum[lane];
            int y = w;
#pragma unroll
            for (int off = 1; off < 32; off <<= 1) {
                int t = __shfl_up_sync(0xffffffffu, y, off);
                if (lane >= off) y += t;
            }
            wsum[lane] = y - w;
        }
        __syncthreads();
        int excl = xs - v + wsum[wid];
        if (tid == 1023) {
            g_aggval[bid] = excl + v;
            __threadfence();
            atomicExch(&g_aggflag[bid], 1);
        }
        if (wid == 0) {
            int acc = 0;
            for (int j = lane; j < bid; j += 32) {
                while (atomicAdd(&g_aggflag[j], 0) == 0) {}
                acc += atomicAdd(&g_aggval[j], 0);
            }
#pragma unroll
            for (int off = 16; off; off >>= 1)
                acc += __shfl_xor_sync(0xffffffffu, acc, off);
            if (lane == 0) bprefix = acc;
        }
        __syncthreads();
        int o = excl + bprefix;
        if (idx < n) {
            g_off[idx] = o;
            g_cursor[idx] = o;
        }
        if (bid == nb - 1 && tid == 1023) g_off[n] = o + v;
        __threadfence();
        __syncthreads();
        if (tid == 0) atomicAdd(&g_done, 1);
    }
    if (tid == 0) while (atomicAdd(&g_done, 0) < nb) {}
    __syncthreads();

    // phase 3: CSR fill
    for (int e = bid * 1024 + tid; e < nE; e += stride) {
        int src = load_idx(ei, e);
        if ((unsigned)src >= (unsigned)n) continue;
        int pos = atomicAdd(&g_cursor[src], 1);
        g_eid[pos] = e;
    }
    grid_bar(&g_done2, nblk);

    // phase 4: gather + comb (one warp per node, MLP-8)
    const float4* ea4 = reinterpret_cast<const float4*>(ea);
    uint2* ch = reinterpret_cast<uint2*>(g_combh);
    uint2* cl = reinterpret_cast<uint2*>(g_combl);
    int gw = (bid * 1024 + tid) >> 5;
    int nw = stride >> 5;
    for (int node = gw; node < n; node += nw) {
        int beg = g_off[node];
        int d = g_off[node + 1] - beg;

        float4 a0 = make_float4(0.f, 0.f, 0.f, 0.f);
        float4 a1 = a0, a2 = a0, a3 = a0;
        float4 a4 = a0, a5 = a0, a6 = a0, a7 = a0;
        for (int base = 0; base < d; base += 32) {
            int m = min(32, d - base);
            int eid = (lane < m) ? g_eid[beg + base + lane] : 0;
            int i = 0;
            for (; i + 8 <= m; i += 8) {
                int e0 = __shfl_sync(0xffffffffu, eid, i);
                int e1 = __shfl_sync(0xffffffffu, eid, i + 1);
                int e2 = __shfl_sync(0xffffffffu, eid, i + 2);
                int e3 = __shfl_sync(0xffffffffu, eid, i + 3);
                int e4 = __shfl_sync(0xffffffffu, eid, i + 4);
                int e5 = __shfl_sync(0xffffffffu, eid, i + 5);
                int e6 = __shfl_sync(0xffffffffu, eid, i + 6);
                int e7 = __shfl_sync(0xffffffffu, eid, i + 7);
                float4 v0 = __ldcs(ea4 + (size_t)e0 * 32 + lane);
                float4 v1 = __ldcs(ea4 + (size_t)e1 * 32 + lane);
                float4 v2 = __ldcs(ea4 + (size_t)e2 * 32 + lane);
                float4 v3 = __ldcs(ea4 + (size_t)e3 * 32 + lane);
                float4 v4 = __ldcs(ea4 + (size_t)e4 * 32 + lane);
                float4 v5 = __ldcs(ea4 + (size_t)e5 * 32 + lane);
                float4 v6 = __ldcs(ea4 + (size_t)e6 * 32 + lane);
                float4 v7 = __ldcs(ea4 + (size_t)e7 * 32 + lane);
                a0.x += v0.x; a0.y += v0.y; a0.z += v0.z; a0.w += v0.w;
                a1.x += v1.x; a1.y += v1.y; a1.z += v1.z; a1.w += v1.w;
                a2.x += v2.x; a2.y += v2.y; a2.z += v2.z; a2.w += v2.w;
                a3.x += v3.x; a3.y += v3.y; a3.z += v3.z; a3.w += v3.w;
                a4.x += v4.x; a4.y += v4.y; a4.z += v4.z; a4.w += v4.w;
                a5.x += v5.x; a5.y += v5.y; a5.z += v5.z; a5.w += v5.w;
                a6.x += v6.x; a6.y += v6.y; a6.z += v6.z; a6.w += v6.w;
                a7.x += v7.x; a7.y += v7.y; a7.z += v7.z; a7.w += v7.w;
            }
            for (; i + 4 <= m; i += 4) {
                int e0 = __shfl_sync(0xffffffffu, eid, i);
                int e1 = __shfl_sync(0xffffffffu, eid, i + 1);
                int e2 = __shfl_sync(0xffffffffu, eid, i + 2);
                int e3 = __shfl_sync(0xffffffffu, eid, i + 3);
                float4 v0 = __ldcs(ea4 + (size_t)e0 * 32 + lane);
                float4 v1 = __ldcs(ea4 + (size_t)e1 * 32 + lane);
                float4 v2 = __ldcs(ea4 + (size_t)e2 * 32 + lane);
                float4 v3 = __ldcs(ea4 + (size_t)e3 * 32 + lane);
                a0.x += v0.x; a0.y += v0.y; a0.z += v0.z; a0.w += v0.w;
                a1.x += v1.x; a1.y += v1.y; a1.z += v1.z; a1.w += v1.w;
                a2.x += v2.x; a2.y += v2.y; a2.z += v2.z; a2.w += v2.w;
                a3.x += v3.x; a3.y += v3.y; a3.z += v3.z; a3.w += v3.w;
            }
            for (; i < m; i++) {
                int e0 = __shfl_sync(0xffffffffu, eid, i);
                float4 v0 = __ldcs(ea4 + (size_t)e0 * 32 + lane);
                a0.x += v0.x; a0.y += v0.y; a0.z += v0.z; a0.w += v0.w;
            }
        }
        float4 acc;
        acc.x = ((a0.x + a1.x) + (a2.x + a3.x)) + ((a4.x + a5.x) + (a6.x + a7.x));
        acc.y = ((a0.y + a1.y) + (a2.y + a3.y)) + ((a4.y + a5.y) + (a6.y + a7.y));
        acc.z = ((a0.z + a1.z) + (a2.z + a3.z)) + ((a4.z + a5.z) + (a6.z + a7.z));
        acc.w = ((a0.w + a1.w) + (a2.w + a3.w)) + ((a4.w + a5.w) + (a6.w + a7.w));
        float inv = 1.f / fmaxf((float)d, 1.f);
        acc.x *= inv; acc.y *= inv; acc.z *= inv; acc.w *= inv;

        float4 xv = reinterpret_cast<const float4*>(x)[(size_t)node * 32 + lane];

        size_t cb = (size_t)node * 64;
        uint2 H, L;
        split4(xv, H, L);  ch[cb + lane] = H;      cl[cb + lane] = L;
        split4(acc, H, L); ch[cb + 32 + lane] = H; cl[cb + 32 + lane] = L;
    }
}

__global__ void fold_kernel(const float* __restrict__ stats,
                            const float* __restrict__ gamma,
                            const float* __restrict__ beta,
                            const float* __restrict__ Wn,
                            const float* __restrict__ bn,
                            bf16* __restrict__ Wh, bf16* __restrict__ Wl,
                            float* __restrict__ bf, float n) {
    __shared__ float a[128], c[128];
    int tid = threadIdx.x;
    float m = stats[tid] / n;
    float var = stats[128 + tid] / n - m * m;
    float rs = rsqrtf(var + BN_EPS);
    a[tid] = gamma[tid] * rs;
    c[tid] = beta[tid] - gamma[tid] * m * rs;
    __syncthreads();
    float accb = 0.f;
#pragma unroll 4
    for (int k = 0; k < 128; k++) {
        float w = Wn[tid * 128 + k];
        float wf = w * a[k];
        bf16 h = __float2bfloat16_rn(wf);
        Wh[tid * 128 + k] = h;
        Wl[tid * 128 + k] = __float2bfloat16_rn(wf - __bfloat162float(h));
        accb += c[k] * w;
    }
    bf[tid] = bn[tid] + accb;
}

// final BN: compute scale/shift from stats in-block, apply to out
__global__ void norm_kernel(float* __restrict__ out,
                            const float* __restrict__ stats,
                            const float* __restrict__ gamma,
                            const float* __restrict__ beta,
                            float fn, int n) {
    __shared__ float sa[128], sc[128];
    int tid = threadIdx.x;
    if (tid < 128) {
        float m = stats[tid] / fn;
        float var = stats[128 + tid] / fn - m * m;
        float rs = rsqrtf(var + BN_EPS);
        sa[tid] = gamma[tid] * rs;
        sc[tid] = beta[tid] - gamma[tid] * m * rs;
    }
    __syncthreads();
    int i = blockIdx.x * blockDim.x + tid;
    int stride = gridDim.x * blockDim.x;
    float4* o4 = reinterpret_cast<float4*>(out);
    const float4* a4 = reinterpret_cast<const float4*>(sa);
    const float4* c4 = reinterpret_cast<const float4*>(sc);
    for (int j = i; j < n * 32; j += stride) {
        int q = j & 31;
        float4 v = o4[j];
        float4 a = a4[q];
        float4 c = c4[q];
        v.x = v.x * a.x + c.x;
        v.y = v.y * a.y + c.y;
        v.z = v.z * a.z + c.z;
        v.w = v.w * a.w + c.w;
        o4[j] = v;
    }
}

// ====================== mma.sync bf16-split GEMM (R9 config) =================
__device__ __forceinline__ void mma16816(float* c, const uint32_t* a,
                                         uint32_t b0, uint32_t b1) {
    asm volatile(
        "mma.sync.aligned.m16n8k16.row.col.f32.bf16.bf16.f32 "
        "{%0,%1,%2,%3}, {%4,%5,%6,%7}, {%8,%9}, {%0,%1,%2,%3};"
        : "+f"(c[0]), "+f"(c[1]), "+f"(c[2]), "+f"(c[3])
        : "r"(a[0]), "r"(a[1]), "r"(a[2]), "r"(a[3]), "r"(b0), "r"(b1));
}

static constexpr int KCH = 32;
static constexpr int LDSTR = 40;
static constexpr int TILE_ELEMS = 128 * LDSTR;
static constexpr int TILE_B = TILE_ELEMS * 2;
static constexpr int STAGE_B = 4 * TILE_B;
static constexpr int GEMM_SMEM = 2 * STAGE_B + 3 * 128 * 4;

template <int K, bool LAST, bool UBIAS>
__global__ void __launch_bounds__(256, 2)
gemm_mma(const bf16* __restrict__ Ah, const bf16* __restrict__ Al,
         const bf16* __restrict__ Wh, const bf16* __restrict__ Wl,
         const float* __restrict__ bias, const float* __restrict__ ubias,
         const void* __restrict__ batch, float* __restrict__ outF,
         bf16* __restrict__ Ch, bf16* __restrict__ Cl,
         float* __restrict__ stats, int n) {
    extern __shared__ __align__(16) char dsm[];
    float* red0 = reinterpret_cast<float*>(dsm + 2 * STAGE_B);
    float* red1 = red0 + 128;
    float* sbias = red1 + 128;

    const int tid = threadIdx.x;
    const int wid = tid >> 5;
    const int lane = tid & 31;
    const int warp_m = wid & 3;
    const int warp_n = wid >> 2;
    const int groupID = lane >> 2;
    const int tig = lane & 3;
    const int rowBase = blockIdx.x * 128;

    const int lrow = tid >> 1;
    const int lh16 = (tid & 1) * 16;
    const bool rowOK = (rowBase + lrow) < n;
    const int arow = rowOK ? (rowBase + lrow) : (n - 1);
    const uint32_t aSz = rowOK ? 16u : 0u;

    const uint32_t sb = smem_u32(dsm);
    const uint32_t rowoff = (uint32_t)(lrow * LDSTR + lh16) * 2;

    const char* gAh = reinterpret_cast<const char*>(Ah + (size_t)arow * K + lh16);
    const char* gAl = reinterpret_cast<const char*>(Al + (size_t)arow * K + lh16);
    const char* gWh = reinterpret_cast<const char*>(Wh + (size_t)lrow * K + lh16);
    const char* gWl = reinterpret_cast<const char*>(Wl + (size_t)lrow * K + lh16);

    constexpr int NC = K / KCH;

    {
        uint32_t s0 = sb + rowoff;
#pragma unroll
        for (int i = 0; i < 2; i++) {
            CP_ASYNC16(s0 + 0 * TILE_B + i * 16, gAh + i * 16, aSz);
            CP_ASYNC16(s0 + 1 * TILE_B + i * 16, gAl + i * 16, aSz);
            CP_ASYNC16(s0 + 2 * TILE_B + i * 16, gWh + i * 16, 16u);
            CP_ASYNC16(s0 + 3 * TILE_B + i * 16, gWl + i * 16, 16u);
        }
        CP_COMMIT();
    }

    if (tid < 128) {
        red0[tid] = 0.f;
        red1[tid] = 0.f;
        if (!UBIAS) sbias[tid] = bias[tid];
    }

    float acc[2][8][4];
#pragma unroll
    for (int mt = 0; mt < 2; mt++)
#pragma unroll
        for (int nt = 0; nt < 8; nt++)
#pragma unroll
            for (int q = 0; q < 4; q++) acc[mt][nt][q] = 0.f;

#pragma unroll 1
    for (int c = 0; c < NC; c++) {
        if (c + 1 < NC) {
            uint32_t s1 = sb + ((c + 1) & 1) * STAGE_B + rowoff;
            int koff = (c + 1) * (KCH * 2);
#pragma unroll
            for (int i = 0; i < 2; i++) {
                CP_ASYNC16(s1 + 0 * TILE_B + i * 16, gAh + koff + i * 16, aSz);
                CP_ASYNC16(s1 + 1 * TILE_B + i * 16, gAl + koff + i * 16, aSz);
                CP_ASYNC16(s1 + 2 * TILE_B + i * 16, gWh + koff + i * 16, 16u);
                CP_ASYNC16(s1 + 3 * TILE_B + i * 16, gWl + koff + i * 16, 16u);
            }
            CP_COMMIT();
            CP_WAIT1();
        } else {
            CP_WAIT0();
        }
        __syncthreads();

        const char* stg = dsm + (c & 1) * STAGE_B;
        const bf16* sAh = reinterpret_cast<const bf16*>(stg);
        const bf16* sAl = sAh + TILE_ELEMS;
        const bf16* sWh = sAl + TILE_ELEMS;
        const bf16* sWl = sWh + TILE_ELEMS;

#pragma unroll
        for (int kk = 0; kk < 2; kk++) {
            const int ac = kk * 16 + tig * 2;
            uint32_t aH[2][4], aL[2][4];
#pragma unroll
            for (int mt = 0; mt < 2; mt++) {
                int r = warp_m * 32 + mt * 16 + groupID;
                const bf16* pH = sAh + r * LDSTR + ac;
                const bf16* pL = sAl + r * LDSTR + ac;
                aH[mt][0] = *reinterpret_cast<const uint32_t*>(pH);
                aH[mt][1] = *reinterpret_cast<const uint32_t*>(pH + 8 * LDSTR);
                aH[mt][2] = *reinterpret_cast<const uint32_t*>(pH + 8);
                aH[mt][3] = *reinterpret_cast<const uint32_t*>(pH + 8 * LDSTR + 8);
                aL[mt][0] = *reinterpret_cast<const uint32_t*>(pL);
                aL[mt][1] = *reinterpret_cast<const uint32_t*>(pL + 8 * LDSTR);
                aL[mt][2] = *reinterpret_cast<const uint32_t*>(pL + 8);
                aL[mt][3] = *reinterpret_cast<const uint32_t*>(pL + 8 * LDSTR + 8);
            }
#pragma unroll
            for (int nt = 0; nt < 8; nt++) {
                int wr = warp_n * 64 + nt * 8 + groupID;
                const bf16* qH = sWh + wr * LDSTR + ac;
                const bf16* qL = sWl + wr * LDSTR + ac;
                uint32_t bH0 = *reinterpret_cast<const uint32_t*>(qH);
                uint32_t bH1 = *reinterpret_cast<const uint32_t*>(qH + 8);
                uint32_t bL0 = *reinterpret_cast<const uint32_t*>(qL);
                uint32_t bL1 = *reinterpret_cast<const uint32_t*>(qL + 8);
#pragma unroll
                for (int mt = 0; mt < 2; mt++) {
                    mma16816(acc[mt][nt], aH[mt], bH0, bH1);
                    mma16816(acc[mt][nt], aL[mt], bH0, bH1);
                    mma16816(acc[mt][nt], aH[mt], bL0, bL1);
                }
            }
        }
        __syncthreads();
    }

    // ---------------- epilogue: bias + relu + stats + store ----------------
#pragma unroll
    for (int mt = 0; mt < 2; mt++) {
        int r0 = rowBase + warp_m * 32 + mt * 16 + groupID;
        int r1 = r0 + 8;
        const float* ub0 = sbias;
        const float* ub1 = sbias;
        if (UBIAS) {
            int b0i = (r0 < n) ? load_idx(batch, r0) : 0;
            int b1i = (r1 < n) ? load_idx(batch, r1) : 0;
            ub0 = ubias + (size_t)b0i * 128;
            ub1 = ubias + (size_t)b1i * 128;
        }
#pragma unroll
        for (int nt = 0; nt < 8; nt++) {
            int j = warp_n * 64 + nt * 8 + tig * 2;
            float* a = acc[mt][nt];
            float v0 = (r0 < n) ? fmaxf(a[0] + ub0[j], 0.f) : 0.f;
            float v1 = (r0 < n) ? fmaxf(a[1] + ub0[j + 1], 0.f) : 0.f;
            float v2 = (r1 < n) ? fmaxf(a[2] + ub1[j], 0.f) : 0.f;
            float v3 = (r1 < n) ? fmaxf(a[3] + ub1[j + 1], 0.f) : 0.f;

            float s0 = v0 + v2, s1 = v1 + v3;
            float q0 = v0 * v0 + v2 * v2, q1 = v1 * v1 + v3 * v3;
#pragma unroll
            for (int off = 4; off < 32; off <<= 1) {
                s0 += __shfl_xor_sync(0xffffffffu, s0, off);
                s1 += __shfl_xor_sync(0xffffffffu, s1, off);
                q0 += __shfl_xor_sync(0xffffffffu, q0, off);
                q1 += __shfl_xor_sync(0xffffffffu, q1, off);
            }
            if (groupID == 0) {
                atomicAdd(red0 + j, s0);
                atomicAdd(red0 + j + 1, s1);
                atomicAdd(red1 + j, q0);
                atomicAdd(red1 + j + 1, q1);
            }

            if (LAST) {
                if (r0 < n)
                    *reinterpret_cast<float2*>(outF + (size_t)r0 * 128 + j) =
                        make_float2(v0, v1);
                if (r1 < n)
                    *reinterpret_cast<float2*>(outF + (size_t)r1 * 128 + j) =
                        make_float2(v2, v3);
            } else {
                if (r0 < n) {
                    bf16 h0 = __float2bfloat16_rn(v0);
                    bf16 h1 = __float2bfloat16_rn(v1);
                    __nv_bfloat162 hp; hp.x = h0; hp.y = h1;
                    *reinterpret_cast<uint32_t*>(Ch + (size_t)r0 * 128 + j) =
                        *reinterpret_cast<uint32_t*>(&hp);
                    *reinterpret_cast<uint32_t*>(Cl + (size_t)r0 * 128 + j) =
                        pack2bf(v0 - __bfloat162float(h0), v1 - __bfloat162float(h1));
                }
                if (r1 < n) {
                    bf16 h2 = __float2bfloat16_rn(v2);
                    bf16 h3 = __float2bfloat16_rn(v3);
                    __nv_bfloat162 hp; hp.x = h2; hp.y = h3;
                    *reinterpret_cast<uint32_t*>(Ch + (size_t)r1 * 128 + j) =
                        *reinterpret_cast<uint32_t*>(&hp);
                    *reinterpret_cast<uint32_t*>(Cl + (size_t)r1 * 128 + j) =
                        pack2bf(v2 - __bfloat162float(h2), v3 - __bfloat162float(h3));
                }
            }
        }
    }
    __syncthreads();
    if (tid < 128) {
        atomicAdd(&stats[tid], red0[tid]);
        atomicAdd(&stats[128 + tid], red1[tid]);
    }
}

// ============================ host launcher ==================================
extern "C" void kernel_launch(void* const* d_in, const int* in_sizes, int n_in,
                              void* d_out, int out_size) {
    const float* x = (const float*)d_in[0];
    const void* ei = d_in[1];
    const float* ea = (const float*)d_in[2];
    const float* u = (const float*)d_in[3];
    const void* batch = d_in[4];
    const float* W0 = (const float*)d_in[5];
    const float* b0 = (const float*)d_in[6];
    const float* W1 = (const float*)d_in[7];
    const float* b1 = (const float*)d_in[8];
    const float* W2 = (const float*)d_in[9];
    const float* b2 = (const float*)d_in[10];
    const float* g0 = (const float*)d_in[11];
    const float* be0 = (const float*)d_in[12];
    const float* g1 = (const float*)d_in[13];
    const float* be1 = (const float*)d_in[14];
    const float* g2 = (const float*)d_in[15];
    const float* be2 = (const float*)d_in[16];

    int n = in_sizes[0] / DIM;
    int nE = in_sizes[2] / DIM;
    int nG = in_sizes[3] / DIM;
    float* out = (float*)d_out;

    bf16 *combh, *combl, *h0h, *h0l, *h1h, *h1l;
    bf16 *w0h, *w0l, *wf1h, *wf1l, *wf2h, *wf2l;
    float *stats, *bf1, *bf2, *ubias;
    cudaGetSymbolAddress((void**)&combh, g_combh);
    cudaGetSymbolAddress((void**)&combl, g_combl);
    cudaGetSymbolAddress((void**)&h0h, g_h0h);
    cudaGetSymbolAddress((void**)&h0l, g_h0l);
    cudaGetSymbolAddress((void**)&h1h, g_h1h);
    cudaGetSymbolAddress((void**)&h1l, g_h1l);
    cudaGetSymbolAddress((void**)&w0h, g_w0h);
    cudaGetSymbolAddress((void**)&w0l, g_w0l);
    cudaGetSymbolAddress((void**)&wf1h, g_wf1h);
    cudaGetSymbolAddress((void**)&wf1l, g_wf1l);
    cudaGetSymbolAddress((void**)&wf2h, g_wf2h);
    cudaGetSymbolAddress((void**)&wf2l, g_wf2l);
    cudaGetSymbolAddress((void**)&stats, g_stats);
    cudaGetSymbolAddress((void**)&bf1, g_bf1);
    cudaGetSymbolAddress((void**)&bf2, g_bf2);
    cudaGetSymbolAddress((void**)&ubias, g_ubias);

    cudaFuncSetAttribute(gemm_mma<KC0, false, true>,
                         cudaFuncAttributeMaxDynamicSharedMemorySize, GEMM_SMEM);
    cudaFuncSetAttribute(gemm_mma<DIM, false, false>,
                         cudaFuncAttributeMaxDynamicSharedMemorySize, GEMM_SMEM);
    cudaFuncSetAttribute(gemm_mma<DIM, true, false>,
                         cudaFuncAttributeMaxDynamicSharedMemorySize, GEMM_SMEM);

    int nb = (n + 1023) / 1024;

    prep_kernel<<<256, 256>>>((const int*)ei, W0, b0, u, nG);
    graph_kernel<<<148, 1024>>>(ei, ea, x, nE, n, nb);

    int gblocks = (n + 127) / 128;
    gemm_mma<KC0, false, true><<<gblocks, 256, GEMM_SMEM>>>(
        combh, combl, w0h, w0l, nullptr, ubias, batch, nullptr, h0h, h0l, stats, n);
    fold_kernel<<<1, 128>>>(stats, g0, be0, W1, b1, wf1h, wf1l, bf1, (float)n);
    gemm_mma<DIM, false, false><<<gblocks, 256, GEMM_SMEM>>>(
        h0h, h0l, wf1h, wf1l, bf1, nullptr, nullptr, nullptr, h1h, h1l,
        stats + 256, n);
    fold_kernel<<<1, 128>>>(stats + 256, g1, be1, W2, b2, wf2h, wf2l, bf2, (float)n);
    gemm_mma<DIM, true, false><<<gblocks, 256, GEMM_SMEM>>>(
        h1h, h1l, wf2h, wf2l, bf2, nullptr, nullptr, out, nullptr, nullptr,
        stats + 512, n);
    norm_kernel<<<1024, 256>>>(out, stats + 512, g2, be2, (float)n, n);
}

// round 15
// speedup vs baseline: 1.0013x; 1.0013x over previous
#include <cuda_runtime.h>
#include <cuda_bf16.h>
#include <cstdint>

#define NN 50000
#define NE 600000
#define DIM 128
#define KC0 256
#define BN_EPS 1e-5f

typedef __nv_bfloat16 bf16;

// ============================ scratch globals ================================
__device__ int g_deg[NN];
__device__ int g_off[NN + 1];
__device__ int g_cursor[NN];
__device__ int g_eid[NE];
__device__ int g_aggval[64];
__device__ int g_aggflag[64];
__device__ int g_bar0, g_bar1, g_done, g_done2;
__device__ bf16 g_combh[NN * KC0];
__device__ bf16 g_combl[NN * KC0];
__device__ bf16 g_h0h[NN * DIM];
__device__ bf16 g_h0l[NN * DIM];
__device__ bf16 g_h1h[NN * DIM];
__device__ bf16 g_h1l[NN * DIM];
__device__ bf16 g_w0h[DIM * KC0];
__device__ bf16 g_w0l[DIM * KC0];
__device__ bf16 g_wf1h[DIM * DIM];
__device__ bf16 g_wf1l[DIM * DIM];
__device__ bf16 g_wf2h[DIM * DIM];
__device__ bf16 g_wf2l[DIM * DIM];
__device__ float g_ubias[DIM * DIM];
__device__ float g_bf1[DIM];
__device__ float g_bf2[DIM];
__device__ float g_stats[3 * 2 * DIM];
__device__ int g_is64;

__device__ __forceinline__ uint32_t pack2bf(float a, float b) {
    __nv_bfloat162 t = __floats2bfloat162_rn(a, b);
    return *reinterpret_cast<uint32_t*>(&t);
}

__device__ __forceinline__ uint32_t smem_u32(const void* p) {
    uint32_t a;
    asm("{ .reg .u64 t; cvta.to.shared.u64 t, %1; cvt.u32.u64 %0, t; }"
        : "=r"(a) : "l"(p));
    return a;
}

#define CP_ASYNC16(dst, src, sz) \
    asm volatile("cp.async.ca.shared.global [%0], [%1], 16, %2;" \
                 :: "r"(dst), "l"(src), "r"(sz))
#define CP_COMMIT() asm volatile("cp.async.commit_group;" ::: "memory")
#define CP_WAIT0() asm volatile("cp.async.wait_group 0;" ::: "memory")
#define CP_WAIT1() asm volatile("cp.async.wait_group 1;" ::: "memory")

__device__ __forceinline__ int load_idx(const void* p, int i) {
    if (g_is64) return (int)((const long long*)p)[i];
    return ((const int*)p)[i];
}

// grid-wide spin barrier for persistent kernel (all blocks resident)
__device__ __forceinline__ void grid_bar(int* ctr, int nblk) {
    __threadfence();
    __syncthreads();
    if (threadIdx.x == 0) {
        atomicAdd(ctr, 1);
        while (atomicAdd(ctr, 0) < nblk) {}
    }
    __syncthreads();
}

// == prep: detect dtype + zero small scratch + split W0 + per-graph ubias ====
__global__ void prep_kernel(const int* __restrict__ ei32,
                            const float* __restrict__ W0,
                            const float* __restrict__ b0,
                            const float* __restrict__ u, int nG) {
    int gtid = blockIdx.x * blockDim.x + threadIdx.x;
    int stride = gridDim.x * blockDim.x;
    if (blockIdx.x == 0) {
        __shared__ int any;
        if (threadIdx.x == 0) any = 0;
        __syncthreads();
        for (int i = threadIdx.x; i < 1024; i += blockDim.x)
            if (ei32[2 * i + 1] != 0) atomicOr(&any, 1);
        __syncthreads();
        if (threadIdx.x == 0) g_is64 = (any == 0) ? 1 : 0;
    }
    for (int j = gtid; j < 3 * 2 * DIM; j += stride) g_stats[j] = 0.f;
    for (int j = gtid; j < 64; j += stride) g_aggflag[j] = 0;
    if (gtid == 0) { g_bar0 = 0; g_bar1 = 0; g_done = 0; g_done2 = 0; }
    for (int i = gtid; i < DIM * KC0; i += stride) {
        int row = i >> 8;
        int col = i & 255;
        float w = W0[row * 384 + col];
        bf16 h = __float2bfloat16_rn(w);
        g_w0h[i] = h;
        g_w0l[i] = __float2bfloat16_rn(w - __bfloat162float(h));
    }
    int g = (int)blockIdx.x - 128;
    if (g >= 0 && g < nG && threadIdx.x < 128) {
        __shared__ float su[128];
        int j = threadIdx.x;
        su[j] = u[g * 128 + j];
        __syncthreads();
        const float* w = W0 + (size_t)j * 384 + 256;
        float acc = b0[j];
#pragma unroll 4
        for (int k = 0; k < 128; k++) acc += su[k] * w[k];
        g_ubias[g * 128 + j] = acc;
    }
}

__device__ __forceinline__ void split4(float4 v, uint2& H, uint2& L) {
    bf16 h0 = __float2bfloat16_rn(v.x);
    bf16 h1 = __float2bfloat16_rn(v.y);
    bf16 h2 = __float2bfloat16_rn(v.z);
    bf16 h3 = __float2bfloat16_rn(v.w);
    float l0 = v.x - __bfloat162float(h0);
    float l1 = v.y - __bfloat162float(h1);
    float l2 = v.z - __bfloat162float(h2);
    float l3 = v.w - __bfloat162float(h3);
    __nv_bfloat162 p01; p01.x = h0; p01.y = h1;
    __nv_bfloat162 p23; p23.x = h2; p23.y = h3;
    H.x = *reinterpret_cast<uint32_t*>(&p01);
    H.y = *reinterpret_cast<uint32_t*>(&p23);
    L.x = pack2bf(l0, l1);
    L.y = pack2bf(l2, l3);
}

// == persistent: zero-deg + hist + scan + CSR fill + gather/comb =============
__global__ void __launch_bounds__(1024, 1)
graph_kernel(const void* __restrict__ ei,
             const float* __restrict__ ea,
             const float* __restrict__ x,
             int nE, int n, int nb) {
    int tid = threadIdx.x;
    int bid = blockIdx.x;
    int lane = tid & 31;
    int wid = tid >> 5;
    int nblk = (int)gridDim.x;
    int stride = nblk * 1024;

    // phase 0: zero degree counters
    for (int j = bid * 1024 + tid; j < n; j += stride) g_deg[j] = 0;
    grid_bar(&g_bar0, nblk);

    // phase 1: histogram
    for (int e = bid * 1024 + tid; e < nE; e += stride) {
        int src = load_idx(ei, e);
        if ((unsigned)src < (unsigned)n) atomicAdd(&g_deg[src], 1);
    }
    grid_bar(&g_bar1, nblk);

    // phase 2: scan with decoupled lookback (blocks < nb)
    if (bid < nb) {
        __shared__ int wsum[32];
        __shared__ int bprefix;
        int idx = bid * 1024 + tid;
        int v = (idx < n) ? g_deg[idx] : 0;
        int xs = v;
#pragma unroll
        for (int off = 1; off < 32; off <<= 1) {
            int t = __shfl_up_sync(0xffffffffu, xs, off);
            if (lane >= off) xs += t;
        }
        if (lane == 31) wsum[wid] = xs;
        __syncthreads();
        if (wid == 0) {
            int w = wsum[lane];
            int y = w;
#pragma unroll
            for (int off = 1; off < 32; off <<= 1) {
                int t = __shfl_up_sync(0xffffffffu, y, off);
                if (lane >= off) y += t;
            }
            wsum[lane] = y - w;
        }
        __syncthreads();
        int excl = xs - v + wsum[wid];
        if (tid == 1023) {
            g_aggval[bid] = excl + v;
            __threadfence();
            atomicExch(&g_aggflag[bid], 1);
        }
        if (wid == 0) {
            int acc = 0;
            for (int j = lane; j < bid; j += 32) {
                while (atomicAdd(&g_aggflag[j], 0) == 0) {}
                acc += atomicAdd(&g_aggval[j], 0);
            }
#pragma unroll
            for (int off = 16; off; off >>= 1)
                acc += __shfl_xor_sync(0xffffffffu, acc, off);
            if (lane == 0) bprefix = acc;
        }
        __syncthreads();
        int o = excl + bprefix;
        if (idx < n) {
            g_off[idx] = o;
            g_cursor[idx] = o;
        }
        if (bid == nb - 1 && tid == 1023) g_off[n] = o + v;
        __threadfence();
        __syncthreads();
        if (tid == 0) atomicAdd(&g_done, 1);
    }
    if (tid == 0) while (atomicAdd(&g_done, 0) < nb) {}
    __syncthreads();

    // phase 3: CSR fill
    for (int e = bid * 1024 + tid; e < nE; e += stride) {
        int src = load_idx(ei, e);
        if ((unsigned)src >= (unsigned)n) continue;
        int pos = atomicAdd(&g_cursor[src], 1);
        g_eid[pos] = e;
    }
    grid_bar(&g_done2, nblk);

    // phase 4: gather + comb (one warp per node, MLP-8)
    const float4* ea4 = reinterpret_cast<const float4*>(ea);
    uint2* ch = reinterpret_cast<uint2*>(g_combh);
    uint2* cl = reinterpret_cast<uint2*>(g_combl);
    int gw = (bid * 1024 + tid) >> 5;
    int nw = stride >> 5;
    for (int node = gw; node < n; node += nw) {
        int beg = g_off[node];
        int d = g_off[node + 1] - beg;

        float4 a0 = make_float4(0.f, 0.f, 0.f, 0.f);
        float4 a1 = a0, a2 = a0, a3 = a0;
        float4 a4 = a0, a5 = a0, a6 = a0, a7 = a0;
        for (int base = 0; base < d; base += 32) {
            int m = min(32, d - base);
            int eid = (lane < m) ? g_eid[beg + base + lane] : 0;
            int i = 0;
            for (; i + 8 <= m; i += 8) {
                int e0 = __shfl_sync(0xffffffffu, eid, i);
                int e1 = __shfl_sync(0xffffffffu, eid, i + 1);
                int e2 = __shfl_sync(0xffffffffu, eid, i + 2);
                int e3 = __shfl_sync(0xffffffffu, eid, i + 3);
                int e4 = __shfl_sync(0xffffffffu, eid, i + 4);
                int e5 = __shfl_sync(0xffffffffu, eid, i + 5);
                int e6 = __shfl_sync(0xffffffffu, eid, i + 6);
                int e7 = __shfl_sync(0xffffffffu, eid, i + 7);
                float4 v0 = __ldcs(ea4 + (size_t)e0 * 32 + lane);
                float4 v1 = __ldcs(ea4 + (size_t)e1 * 32 + lane);
                float4 v2 = __ldcs(ea4 + (size_t)e2 * 32 + lane);
                float4 v3 = __ldcs(ea4 + (size_t)e3 * 32 + lane);
                float4 v4 = __ldcs(ea4 + (size_t)e4 * 32 + lane);
                float4 v5 = __ldcs(ea4 + (size_t)e5 * 32 + lane);
                float4 v6 = __ldcs(ea4 + (size_t)e6 * 32 + lane);
                float4 v7 = __ldcs(ea4 + (size_t)e7 * 32 + lane);
                a0.x += v0.x; a0.y += v0.y; a0.z += v0.z; a0.w += v0.w;
                a1.x += v1.x; a1.y += v1.y; a1.z += v1.z; a1.w += v1.w;
                a2.x += v2.x; a2.y += v2.y; a2.z += v2.z; a2.w += v2.w;
                a3.x += v3.x; a3.y += v3.y; a3.z += v3.z; a3.w += v3.w;
                a4.x += v4.x; a4.y += v4.y; a4.z += v4.z; a4.w += v4.w;
                a5.x += v5.x; a5.y += v5.y; a5.z += v5.z; a5.w += v5.w;
                a6.x += v6.x; a6.y += v6.y; a6.z += v6.z; a6.w += v6.w;
                a7.x += v7.x; a7.y += v7.y; a7.z += v7.z; a7.w += v7.w;
            }
            for (; i + 4 <= m; i += 4) {
                int e0 = __shfl_sync(0xffffffffu, eid, i);
                int e1 = __shfl_sync(0xffffffffu, eid, i + 1);
                int e2 = __shfl_sync(0xffffffffu, eid, i + 2);
                int e3 = __shfl_sync(0xffffffffu, eid, i + 3);
                float4 v0 = __ldcs(ea4 + (size_t)e0 * 32 + lane);
                float4 v1 = __ldcs(ea4 + (size_t)e1 * 32 + lane);
                float4 v2 = __ldcs(ea4 + (size_t)e2 * 32 + lane);
                float4 v3 = __ldcs(ea4 + (size_t)e3 * 32 + lane);
                a0.x += v0.x; a0.y += v0.y; a0.z += v0.z; a0.w += v0.w;
                a1.x += v1.x; a1.y += v1.y; a1.z += v1.z; a1.w += v1.w;
                a2.x += v2.x; a2.y += v2.y; a2.z += v2.z; a2.w += v2.w;
                a3.x += v3.x; a3.y += v3.y; a3.z += v3.z; a3.w += v3.w;
            }
            for (; i < m; i++) {
                int e0 = __shfl_sync(0xffffffffu, eid, i);
                float4 v0 = __ldcs(ea4 + (size_t)e0 * 32 + lane);
                a0.x += v0.x; a0.y += v0.y; a0.z += v0.z; a0.w += v0.w;
            }
        }
        float4 acc;
        acc.x = ((a0.x + a1.x) + (a2.x + a3.x)) + ((a4.x + a5.x) + (a6.x + a7.x));
        acc.y = ((a0.y + a1.y) + (a2.y + a3.y)) + ((a4.y + a5.y) + (a6.y + a7.y));
        acc.z = ((a0.z + a1.z) + (a2.z + a3.z)) + ((a4.z + a5.z) + (a6.z + a7.z));
        acc.w = ((a0.w + a1.w) + (a2.w + a3.w)) + ((a4.w + a5.w) + (a6.w + a7.w));
        float inv = 1.f / fmaxf((float)d, 1.f);
        acc.x *= inv; acc.y *= inv; acc.z *= inv; acc.w *= inv;

        float4 xv = reinterpret_cast<const float4*>(x)[(size_t)node * 32 + lane];

        size_t cb = (size_t)node * 64;
        uint2 H, L;
        split4(xv, H, L);  ch[cb + lane] = H;      cl[cb + lane] = L;
        split4(acc, H, L); ch[cb + 32 + lane] = H; cl[cb + 32 + lane] = L;
    }
}

__global__ void fold_kernel(const float* __restrict__ stats,
                            const float* __restrict__ gamma,
                            const float* __restrict__ beta,
                            const float* __restrict__ Wn,
                            const float* __restrict__ bn,
                            bf16* __restrict__ Wh, bf16* __restrict__ Wl,
                            float* __restrict__ bf, float n) {
    __shared__ float a[128], c[128];
    int tid = threadIdx.x;
    float m = stats[tid] / n;
    float var = stats[128 + tid] / n - m * m;
    float rs = rsqrtf(var + BN_EPS);
    a[tid] = gamma[tid] * rs;
    c[tid] = beta[tid] - gamma[tid] * m * rs;
    __syncthreads();
    float accb = 0.f;
#pragma unroll 4
    for (int k = 0; k < 128; k++) {
        float w = Wn[tid * 128 + k];
        float wf = w * a[k];
        bf16 h = __float2bfloat16_rn(wf);
        Wh[tid * 128 + k] = h;
        Wl[tid * 128 + k] = __float2bfloat16_rn(wf - __bfloat162float(h));
        accb += c[k] * w;
    }
    bf[tid] = bn[tid] + accb;
}

// final BN: compute scale/shift from stats in-block, apply to out
__global__ void norm_kernel(float* __restrict__ out,
                            const float* __restrict__ stats,
                            const float* __restrict__ gamma,
                            const float* __restrict__ beta,
                            float fn, int n) {
    __shared__ float sa[128], sc[128];
    int tid = threadIdx.x;
    if (tid < 128) {
        float m = stats[tid] / fn;
        float var = stats[128 + tid] / fn - m * m;
        float rs = rsqrtf(var + BN_EPS);
        sa[tid] = gamma[tid] * rs;
        sc[tid] = beta[tid] - gamma[tid] * m * rs;
    }
    __syncthreads();
    int i = blockIdx.x * blockDim.x + tid;
    int stride = gridDim.x * blockDim.x;
    float4* o4 = reinterpret_cast<float4*>(out);
    const float4* a4 = reinterpret_cast<const float4*>(sa);
    const float4* c4 = reinterpret_cast<const float4*>(sc);
    for (int j = i; j < n * 32; j += stride) {
        int q = j & 31;
        float4 v = o4[j];
        float4 a = a4[q];
        float4 c = c4[q];
        v.x = v.x * a.x + c.x;
        v.y = v.y * a.y + c.y;
        v.z = v.z * a.z + c.z;
        v.w = v.w * a.w + c.w;
        o4[j] = v;
    }
}

// ====================== mma.sync bf16-split GEMM (R9 config) =================
__device__ __forceinline__ void mma16816(float* c, const uint32_t* a,
                                         uint32_t b0, uint32_t b1) {
    asm volatile(
        "mma.sync.aligned.m16n8k16.row.col.f32.bf16.bf16.f32 "
        "{%0,%1,%2,%3}, {%4,%5,%6,%7}, {%8,%9}, {%0,%1,%2,%3};"
        : "+f"(c[0]), "+f"(c[1]), "+f"(c[2]), "+f"(c[3])
        : "r"(a[0]), "r"(a[1]), "r"(a[2]), "r"(a[3]), "r"(b0), "r"(b1));
}

static constexpr int KCH = 32;
static constexpr int LDSTR = 40;
static constexpr int TILE_ELEMS = 128 * LDSTR;
static constexpr int TILE_B = TILE_ELEMS * 2;
static constexpr int STAGE_B = 4 * TILE_B;
static constexpr int GEMM_SMEM = 2 * STAGE_B + 3 * 128 * 4;

template <int K, bool LAST, bool UBIAS>
__global__ void __launch_bounds__(256, 2)
gemm_mma(const bf16* __restrict__ Ah, const bf16* __restrict__ Al,
         const bf16* __restrict__ Wh, const bf16* __restrict__ Wl,
         const float* __restrict__ bias, const float* __restrict__ ubias,
         const void* __restrict__ batch, float* __restrict__ outF,
         bf16* __restrict__ Ch, bf16* __restrict__ Cl,
         float* __restrict__ stats, int n) {
    extern __shared__ __align__(16) char dsm[];
    float* red0 = reinterpret_cast<float*>(dsm + 2 * STAGE_B);
    float* red1 = red0 + 128;
    float* sbias = red1 + 128;

    const int tid = threadIdx.x;
    const int wid = tid >> 5;
    const int lane = tid & 31;
    const int warp_m = wid & 3;
    const int warp_n = wid >> 2;
    const int groupID = lane >> 2;
    const int tig = lane & 3;
    const int rowBase = blockIdx.x * 128;

    const int lrow = tid >> 1;
    const int lh16 = (tid & 1) * 16;
    const bool rowOK = (rowBase + lrow) < n;
    const int arow = rowOK ? (rowBase + lrow) : (n - 1);
    const uint32_t aSz = rowOK ? 16u : 0u;

    const uint32_t sb = smem_u32(dsm);
    const uint32_t rowoff = (uint32_t)(lrow * LDSTR + lh16) * 2;

    const char* gAh = reinterpret_cast<const char*>(Ah + (size_t)arow * K + lh16);
    const char* gAl = reinterpret_cast<const char*>(Al + (size_t)arow * K + lh16);
    const char* gWh = reinterpret_cast<const char*>(Wh + (size_t)lrow * K + lh16);
    const char* gWl = reinterpret_cast<const char*>(Wl + (size_t)lrow * K + lh16);

    constexpr int NC = K / KCH;

    {
        uint32_t s0 = sb + rowoff;
#pragma unroll
        for (int i = 0; i < 2; i++) {
            CP_ASYNC16(s0 + 0 * TILE_B + i * 16, gAh + i * 16, aSz);
            CP_ASYNC16(s0 + 1 * TILE_B + i * 16, gAl + i * 16, aSz);
            CP_ASYNC16(s0 + 2 * TILE_B + i * 16, gWh + i * 16, 16u);
            CP_ASYNC16(s0 + 3 * TILE_B + i * 16, gWl + i * 16, 16u);
        }
        CP_COMMIT();
    }

    if (tid < 128) {
        red0[tid] = 0.f;
        red1[tid] = 0.f;
        if (!UBIAS) sbias[tid] = bias[tid];
    }

    float acc[2][8][4];
#pragma unroll
    for (int mt = 0; mt < 2; mt++)
#pragma unroll
        for (int nt = 0; nt < 8; nt++)
#pragma unroll
            for (int q = 0; q < 4; q++) acc[mt][nt][q] = 0.f;

#pragma unroll 1
    for (int c = 0; c < NC; c++) {
        if (c + 1 < NC) {
            uint32_t s1 = sb + ((c + 1) & 1) * STAGE_B + rowoff;
            int koff = (c + 1) * (KCH * 2);
#pragma unroll
            for (int i = 0; i < 2; i++) {
                CP_ASYNC16(s1 + 0 * TILE_B + i * 16, gAh + koff + i * 16, aSz);
                CP_ASYNC16(s1 + 1 * TILE_B + i * 16, gAl + koff + i * 16, aSz);
                CP_ASYNC16(s1 + 2 * TILE_B + i * 16, gWh + koff + i * 16, 16u);
                CP_ASYNC16(s1 + 3 * TILE_B + i * 16, gWl + koff + i * 16, 16u);
            }
            CP_COMMIT();
            CP_WAIT1();
        } else {
            CP_WAIT0();
        }
        __syncthreads();

        const char* stg = dsm + (c & 1) * STAGE_B;
        const bf16* sAh = reinterpret_cast<const bf16*>(stg);
        const bf16* sAl = sAh + TILE_ELEMS;
        const bf16* sWh = sAl + TILE_ELEMS;
        const bf16* sWl = sWh + TILE_ELEMS;

#pragma unroll
        for (int kk = 0; kk < 2; kk++) {
            const int ac = kk * 16 + tig * 2;
            uint32_t aH[2][4], aL[2][4];
#pragma unroll
            for (int mt = 0; mt < 2; mt++) {
                int r = warp_m * 32 + mt * 16 + groupID;
                const bf16* pH = sAh + r * LDSTR + ac;
                const bf16* pL = sAl + r * LDSTR + ac;
                aH[mt][0] = *reinterpret_cast<const uint32_t*>(pH);
                aH[mt][1] = *reinterpret_cast<const uint32_t*>(pH + 8 * LDSTR);
                aH[mt][2] = *reinterpret_cast<const uint32_t*>(pH + 8);
                aH[mt][3] = *reinterpret_cast<const uint32_t*>(pH + 8 * LDSTR + 8);
                aL[mt][0] = *reinterpret_cast<const uint32_t*>(pL);
                aL[mt][1] = *reinterpret_cast<const uint32_t*>(pL + 8 * LDSTR);
                aL[mt][2] = *reinterpret_cast<const uint32_t*>(pL + 8);
                aL[mt][3] = *reinterpret_cast<const uint32_t*>(pL + 8 * LDSTR + 8);
            }
#pragma unroll
            for (int nt = 0; nt < 8; nt++) {
                int wr = warp_n * 64 + nt * 8 + groupID;
                const bf16* qH = sWh + wr * LDSTR + ac;
                const bf16* qL = sWl + wr * LDSTR + ac;
                uint32_t bH0 = *reinterpret_cast<const uint32_t*>(qH);
                uint32_t bH1 = *reinterpret_cast<const uint32_t*>(qH + 8);
                uint32_t bL0 = *reinterpret_cast<const uint32_t*>(qL);
                uint32_t bL1 = *reinterpret_cast<const uint32_t*>(qL + 8);
#pragma unroll
                for (int mt = 0; mt < 2; mt++) {
                    mma16816(acc[mt][nt], aH[mt], bH0, bH1);
                    mma16816(acc[mt][nt], aL[mt], bH0, bH1);
                    mma16816(acc[mt][nt], aH[mt], bL0, bL1);
                }
            }
        }
        __syncthreads();
    }

    // ---------------- epilogue: bias + relu + stats + store ----------------
#pragma unroll
    for (int mt = 0; mt < 2; mt++) {
        int r0 = rowBase + warp_m * 32 + mt * 16 + groupID;
        int r1 = r0 + 8;
        const float* ub0 = sbias;
        const float* ub1 = sbias;
        if (UBIAS) {
            int b0i = (r0 < n) ? load_idx(batch, r0) : 0;
            int b1i = (r1 < n) ? load_idx(batch, r1) : 0;
            ub0 = ubias + (size_t)b0i * 128;
            ub1 = ubias + (size_t)b1i * 128;
        }
#pragma unroll
        for (int nt = 0; nt < 8; nt++) {
            int j = warp_n * 64 + nt * 8 + tig * 2;
            float* a = acc[mt][nt];
            float v0 = (r0 < n) ? fmaxf(a[0] + ub0[j], 0.f) : 0.f;
            float v1 = (r0 < n) ? fmaxf(a[1] + ub0[j + 1], 0.f) : 0.f;
            float v2 = (r1 < n) ? fmaxf(a[2] + ub1[j], 0.f) : 0.f;
            float v3 = (r1 < n) ? fmaxf(a[3] + ub1[j + 1], 0.f) : 0.f;

            float s0 = v0 + v2, s1 = v1 + v3;
            float q0 = v0 * v0 + v2 * v2, q1 = v1 * v1 + v3 * v3;
#pragma unroll
            for (int off = 4; off < 32; off <<= 1) {
                s0 += __shfl_xor_sync(0xffffffffu, s0, off);
                s1 += __shfl_xor_sync(0xffffffffu, s1, off);
                q0 += __shfl_xor_sync(0xffffffffu, q0, off);
                q1 += __shfl_xor_sync(0xffffffffu, q1, off);
            }
            if (groupID == 0) {
                atomicAdd(red0 + j, s0);
                atomicAdd(red0 + j + 1, s1);
                atomicAdd(red1 + j, q0);
                atomicAdd(red1 + j + 1, q1);
            }

            if (LAST) {
                if (r0 < n)
                    *reinterpret_cast<float2*>(outF + (size_t)r0 * 128 + j) =
                        make_float2(v0, v1);
                if (r1 < n)
                    *reinterpret_cast<float2*>(outF + (size_t)r1 * 128 + j) =
                        make_float2(v2, v3);
            } else {
                if (r0 < n) {
                    bf16 h0 = __float2bfloat16_rn(v0);
                    bf16 h1 = __float2bfloat16_rn(v1);
                    __nv_bfloat162 hp; hp.x = h0; hp.y = h1;
                    *reinterpret_cast<uint32_t*>(Ch + (size_t)r0 * 128 + j) =
                        *reinterpret_cast<uint32_t*>(&hp);
                    *reinterpret_cast<uint32_t*>(Cl + (size_t)r0 * 128 + j) =
                        pack2bf(v0 - __bfloat162float(h0), v1 - __bfloat162float(h1));
                }
                if (r1 < n) {
                    bf16 h2 = __float2bfloat16_rn(v2);
                    bf16 h3 = __float2bfloat16_rn(v3);
                    __nv_bfloat162 hp; hp.x = h2; hp.y = h3;
                    *reinterpret_cast<uint32_t*>(Ch + (size_t)r1 * 128 + j) =
                        *reinterpret_cast<uint32_t*>(&hp);
                    *reinterpret_cast<uint32_t*>(Cl + (size_t)r1 * 128 + j) =
                        pack2bf(v2 - __bfloat162float(h2), v3 - __bfloat162float(h3));
                }
            }
        }
    }
    __syncthreads();
    if (tid < 128) {
        atomicAdd(&stats[tid], red0[tid]);
        atomicAdd(&stats[128 + tid], red1[tid]);
    }
}

// ============================ host launcher ==================================
extern "C" void kernel_launch(void* const* d_in, const int* in_sizes, int n_in,
                              void* d_out, int out_size) {
    const float* x = (const float*)d_in[0];
    const void* ei = d_in[1];
    const float* ea = (const float*)d_in[2];
    const float* u = (const float*)d_in[3];
    const void* batch = d_in[4];
    const float* W0 = (const float*)d_in[5];
    const float* b0 = (const float*)d_in[6];
    const float* W1 = (const float*)d_in[7];
    const float* b1 = (const float*)d_in[8];
    const float* W2 = (const float*)d_in[9];
    const float* b2 = (const float*)d_in[10];
    const float* g0 = (const float*)d_in[11];
    const float* be0 = (const float*)d_in[12];
    const float* g1 = (const float*)d_in[13];
    const float* be1 = (const float*)d_in[14];
    const float* g2 = (const float*)d_in[15];
    const float* be2 = (const float*)d_in[16];

    int n = in_sizes[0] / DIM;
    int nE = in_sizes[2] / DIM;
    int nG = in_sizes[3] / DIM;
    float* out = (float*)d_out;

    bf16 *combh, *combl, *h0h, *h0l, *h1h, *h1l;
    bf16 *w0h, *w0l, *wf1h, *wf1l, *wf2h, *wf2l;
    float *stats, *bf1, *bf2, *ubias;
    cudaGetSymbolAddress((void**)&combh, g_combh);
    cudaGetSymbolAddress((void**)&combl, g_combl);
    cudaGetSymbolAddress((void**)&h0h, g_h0h);
    cudaGetSymbolAddress((void**)&h0l, g_h0l);
    cudaGetSymbolAddress((void**)&h1h, g_h1h);
    cudaGetSymbolAddress((void**)&h1l, g_h1l);
    cudaGetSymbolAddress((void**)&w0h, g_w0h);
    cudaGetSymbolAddress((void**)&w0l, g_w0l);
    cudaGetSymbolAddress((void**)&wf1h, g_wf1h);
    cudaGetSymbolAddress((void**)&wf1l, g_wf1l);
    cudaGetSymbolAddress((void**)&wf2h, g_wf2h);
    cudaGetSymbolAddress((void**)&wf2l, g_wf2l);
    cudaGetSymbolAddress((void**)&stats, g_stats);
    cudaGetSymbolAddress((void**)&bf1, g_bf1);
    cudaGetSymbolAddress((void**)&bf2, g_bf2);
    cudaGetSymbolAddress((void**)&ubias, g_ubias);

    cudaFuncSetAttribute(gemm_mma<KC0, false, true>,
                         cudaFuncAttributeMaxDynamicSharedMemorySize, GEMM_SMEM);
    cudaFuncSetAttribute(gemm_mma<DIM, false, false>,
                         cudaFuncAttributeMaxDynamicSharedMemorySize, GEMM_SMEM);
    cudaFuncSetAttribute(gemm_mma<DIM, true, false>,
                         cudaFuncAttributeMaxDynamicSharedMemorySize, GEMM_SMEM);

    int nb = (n + 1023) / 1024;

    prep_kernel<<<256, 256>>>((const int*)ei, W0, b0, u, nG);
    graph_kernel<<<148, 1024>>>(ei, ea, x, nE, n, nb);

    int gblocks = (n + 127) / 128;
    gemm_mma<KC0, false, true><<<gblocks, 256, GEMM_SMEM>>>(
        combh, combl, w0h, w0l, nullptr, ubias, batch, nullptr, h0h, h0l, stats, n);
    fold_kernel<<<1, 128>>>(stats, g0, be0, W1, b1, wf1h, wf1l, bf1, (float)n);
    gemm_mma<DIM, false, false><<<gblocks, 256, GEMM_SMEM>>>(
        h0h, h0l, wf1h, wf1l, bf1, nullptr, nullptr, nullptr, h1h, h1l,
        stats + 256, n);
    fold_kernel<<<1, 128>>>(stats + 256, g1, be1, W2, b2, wf2h, wf2l, bf2, (float)n);
    gemm_mma<DIM, true, false><<<gblocks, 256, GEMM_SMEM>>>(
        h1h, h1l, wf2h, wf2l, bf2, nullptr, nullptr, out, nullptr, nullptr,
        stats + 512, n);
    norm_kernel<<<1024, 256>>>(out, stats + 512, g2, be2, (float)n, n);
}